// round 14
// baseline (speedup 1.0000x reference)
#include <cuda_runtime.h>
#include <cuda_bf16.h>

// ---------------------------------------------------------------------------
// BSplineBasis: out[N,6] = cubic B-spline basis of min-max-normalized x.
// Knots compile-time ([0,0,0,0,1/3,2/3,1,1,1,1]) => closed-form span cubics.
// Kernel 1: min/max reduction -> g_norm = {scale, -xmin*scale}.
// Kernel 2 (PDL, R11 structure = best total): one-shot grid 8192x256,
//   4 pts/lane, per-warp smem transpose (stride-7 pad), 6 lane-contiguous
//   STG.128 — now with DEFAULT cache policy (no .cs): lets L2 assemble full
//   128-B lines before writeback (TMA runs showed full-line writes reach
//   ~62% DRAM vs 57% with .cs streaming).
//   x loads issued BEFORE cudaGridDependencySynchronize (PDL overlap).
// ---------------------------------------------------------------------------

#define MAXB 592
#define K13 0.33333334f   /* fp32(1/3) */
#define K23 0.6666667f    /* fp32(2/3) */

__device__ unsigned g_pmin[MAXB];
__device__ unsigned g_pmax[MAXB];
__device__ unsigned g_count = 0;     // restored to 0 each run (graph-safe)
__device__ float2   g_norm;          // {scale, nbias = -xmin*scale}

__device__ __forceinline__ unsigned fenc(float f) {
    unsigned u = __float_as_uint(f);
    return (u & 0x80000000u) ? ~u : (u | 0x80000000u);
}
__device__ __forceinline__ float fdec(unsigned u) {
    return (u & 0x80000000u) ? __uint_as_float(u ^ 0x80000000u)
                             : __uint_as_float(~u);
}

__global__ void __launch_bounds__(256)
reduce_setup_kernel(const float* __restrict__ x, int n)
{
    float lmin =  3.4e38f, lmax = -3.4e38f;

    int n4 = n >> 2;
    const float4* __restrict__ x4 = (const float4*)x;
    int stride = gridDim.x * blockDim.x;
    #pragma unroll 8
    for (int i = blockIdx.x * blockDim.x + threadIdx.x; i < n4; i += stride) {
        float4 v = x4[i];
        lmin = fminf(lmin, fminf(fminf(v.x, v.y), fminf(v.z, v.w)));
        lmax = fmaxf(lmax, fmaxf(fmaxf(v.x, v.y), fmaxf(v.z, v.w)));
    }
    for (int i = n4 * 4 + blockIdx.x * blockDim.x + threadIdx.x; i < n; i += stride) {
        float e = x[i];
        lmin = fminf(lmin, e); lmax = fmaxf(lmax, e);
    }

    unsigned emin = __reduce_min_sync(0xFFFFFFFFu, fenc(lmin));
    unsigned emax = __reduce_max_sync(0xFFFFFFFFu, fenc(lmax));

    __shared__ unsigned smin[8], smax[8];
    __shared__ bool is_last;
    int w = threadIdx.x >> 5;
    if ((threadIdx.x & 31) == 0) { smin[w] = emin; smax[w] = emax; }
    __syncthreads();
    if (threadIdx.x == 0) {
        int nw = blockDim.x >> 5;
        for (int i = 1; i < nw; i++) {
            emin = min(emin, smin[i]); emax = max(emax, smax[i]);
        }
        g_pmin[blockIdx.x] = emin;
        g_pmax[blockIdx.x] = emax;
        __threadfence();
        unsigned prev = atomicAdd(&g_count, 1u);
        is_last = (prev == gridDim.x - 1);
    }
    __syncthreads();
    if (!is_last) return;

    unsigned fmn = 0xFFFFFFFFu, fmx = 0u;
    int nb = gridDim.x;
    for (int i = threadIdx.x; i < nb; i += blockDim.x) {
        fmn = min(fmn, __ldcg(&g_pmin[i]));
        fmx = max(fmx, __ldcg(&g_pmax[i]));
    }
    fmn = __reduce_min_sync(0xFFFFFFFFu, fmn);
    fmx = __reduce_max_sync(0xFFFFFFFFu, fmx);
    if ((threadIdx.x & 31) == 0) { smin[w] = fmn; smax[w] = fmx; }
    __syncthreads();
    if (threadIdx.x == 0) {
        int nw = blockDim.x >> 5;
        for (int i = 1; i < nw; i++) {
            fmn = min(fmn, smin[i]); fmx = max(fmx, smax[i]);
        }
        float xmin = fdec(fmn);
        float xmax = fdec(fmx);
        float scale = 1.0f / (xmax - xmin + 1e-8f);
        g_norm = make_float2(scale, -xmin * scale);
        __threadfence();
        g_count = 0;
    }
}

// Closed-form cubic bases per span; coefficients are exact fp32 dyadics.
__device__ __forceinline__ void evalPoint(float u, float* __restrict__ o)
{
    if (u < K13) {
        float N0 = fmaf(u, -27.0f, 27.0f);  N0 = fmaf(u, N0, -9.0f);  N0 = fmaf(u, N0, 1.0f);
        float N1 = fmaf(u, 47.25f, -40.5f); N1 = fmaf(u, N1, 9.0f);   N1 = N1 * u;
        float N2 = fmaf(u, -24.75f, 13.5f); N2 = N2 * (u * u);
        float N3 = 4.5f * u * (u * u);
        o[0] = N0; o[1] = N1; o[2] = N2; o[3] = N3; o[4] = 0.0f; o[5] = 0.0f;
    } else if (u < K23) {
        float N1 = fmaf(u, -6.75f, 13.5f);   N1 = fmaf(u, N1, -9.0f);  N1 = fmaf(u, N1, 2.0f);
        float N2 = fmaf(u, 15.75f, -27.0f);  N2 = fmaf(u, N2, 13.5f);  N2 = fmaf(u, N2, -1.5f);
        float N3 = fmaf(u, -15.75f, 20.25f); N3 = fmaf(u, N3, -6.75f); N3 = fmaf(u, N3, 0.75f);
        float N4 = fmaf(u, 6.75f, -6.75f);   N4 = fmaf(u, N4, 2.25f);  N4 = fmaf(u, N4, -0.25f);
        o[0] = 0.0f; o[1] = N1; o[2] = N2; o[3] = N3; o[4] = N4; o[5] = 0.0f;
    } else {
        float w = 1.0f - u;
        float N5 = fmaf(w, -27.0f, 27.0f);  N5 = fmaf(w, N5, -9.0f);  N5 = fmaf(w, N5, 1.0f);
        float N4 = fmaf(w, 47.25f, -40.5f); N4 = fmaf(w, N4, 9.0f);   N4 = N4 * w;
        float N3 = fmaf(w, -24.75f, 13.5f); N3 = N3 * (w * w);
        float N2 = 4.5f * w * (w * w);
        o[0] = 0.0f; o[1] = 0.0f; o[2] = N2; o[3] = N3; o[4] = N4; o[5] = N5;
    }
}

// Per-warp staging: 32 lanes x 6 float4, padded to stride 7 per lane.
// Write (L = 6*lane + q -> slot 7*lane + q): conflict-free.
// Read  (L = q*32 + lane -> slot L + L/6): near-linear, rare 2-way.
#define WSTAGE 224

__global__ void __launch_bounds__(256)
bspline_main_kernel(const float* __restrict__ x,
                    float* __restrict__ out, int n)
{
    __shared__ float4 stage[8][WSTAGE];

    int lane = threadIdx.x & 31;
    int warp = threadIdx.x >> 5;
    int gwarp = blockIdx.x * 8 + warp;
    int wbase = gwarp * 128;             // first point of this warp

    if (wbase >= n) {
        cudaGridDependencySynchronize();
        return;
    }

    if (wbase + 128 <= n) {
        // Issue the x load BEFORE the dependency sync: it does not depend on
        // the reduction result, so it overlaps the reduce kernel's tail.
        float4 v = __ldg(((const float4*)x) + (wbase >> 2) + lane);

        cudaGridDependencySynchronize();      // g_norm now valid
        float2 nrm = g_norm;
        float scale = nrm.x, nb = nrm.y;

        float xs[4] = {v.x, v.y, v.z, v.w};
        float res[24];
        #pragma unroll
        for (int p = 0; p < 4; p++) {
            float u = fmaf(xs[p], scale, nb);
            evalPoint(u, &res[p * 6]);
        }

        float4* ws = stage[warp];
        #pragma unroll
        for (int q = 0; q < 6; q++)
            ws[7 * lane + q] = make_float4(res[4 * q], res[4 * q + 1],
                                           res[4 * q + 2], res[4 * q + 3]);
        __syncwarp();

        // coalesced stores: 6 x STG.128, 16-B lane stride.
        // DEFAULT cache policy (no .cs): L2 assembles full 128-B lines
        // before writeback -> higher DRAM write efficiency.
        float4* o4 = (float4*)out + (size_t)wbase * 6 / 4;
        #pragma unroll
        for (int q = 0; q < 6; q++) {
            int L = q * 32 + lane;
            o4[L] = ws[L + L / 6];
        }
    } else {
        cudaGridDependencySynchronize();
        float2 nrm = g_norm;
        float scale = nrm.x, nb = nrm.y;
        // tail warp: scalar per-point
        for (int p = lane; p < 128; p += 32) {
            int idx = wbase + p;
            if (idx >= n) break;
            float u = fmaf(x[idx], scale, nb);
            float b6[6];
            evalPoint(u, b6);
            float* o = out + (size_t)idx * 6;
            #pragma unroll
            for (int j = 0; j < 6; j++) o[j] = b6[j];
        }
    }
}

extern "C" void kernel_launch(void* const* d_in, const int* in_sizes, int n_in,
                              void* d_out, int out_size)
{
    const float* x = (const float*)d_in[0];
    float* out     = (float*)d_out;
    int n = in_sizes[0];
    if (n <= 0) return;

    int n4 = n >> 2;
    int rblocks = (n4 + 255) / 256;
    if (rblocks > MAXB) rblocks = MAXB;
    if (rblocks < 1) rblocks = 1;
    reduce_setup_kernel<<<rblocks, 256>>>(x, n);

    int npts_per_block = 1024;           // 8 warps * 128 pts
    int mblocks = (n + npts_per_block - 1) / npts_per_block;

    // PDL launch: main kernel may begin before reduce fully completes;
    // cudaGridDependencySynchronize() inside provides the ordering.
    cudaLaunchConfig_t cfg = {};
    cfg.gridDim  = dim3((unsigned)mblocks);
    cfg.blockDim = dim3(256);
    cfg.dynamicSmemBytes = 0;
    cfg.stream = 0;
    cudaLaunchAttribute attr[1];
    attr[0].id = cudaLaunchAttributeProgrammaticStreamSerialization;
    attr[0].val.programmaticStreamSerializationAllowed = 1;
    cfg.attrs = attr;
    cfg.numAttrs = 1;
    cudaError_t err = cudaLaunchKernelEx(&cfg, bspline_main_kernel, x, out, n);
    if (err != cudaSuccess) {
        // fallback: plain serialized launch
        bspline_main_kernel<<<mblocks, 256>>>(x, out, n);
    }
}

// round 15
// speedup vs baseline: 1.1396x; 1.1396x over previous
#include <cuda_runtime.h>
#include <cuda_bf16.h>

// ---------------------------------------------------------------------------
// BSplineBasis: out[N,6] = cubic B-spline basis of min-max-normalized x.
// Knots compile-time ([0,0,0,0,1/3,2/3,1,1,1,1]) => closed-form span cubics.
// Kernel 1 (PDL): min/max reduction -> g_norm = {scale, -xmin*scale}.
//   NEW: launched with PDL and does its whole x scan BEFORE
//   cudaGridDependencySynchronize() -> in the harness's graph-replay loop,
//   replay k+1's reduce overlaps replay k's main-kernel store drain.
//   Safe: reduce only reads x; g_norm rewrite is bit-identical per replay.
// Kernel 2 (PDL, exact R11 = best total 43.2us): one-shot grid 8192x256,
//   4 pts/lane, per-warp smem transpose (stride-7 pad), 6 lane-contiguous
//   STG.128 with .cs streaming (non-.cs paths defer writeback past kernel
//   end and cost ~6-8us between graph nodes — measured R13/R14).
// ---------------------------------------------------------------------------

#define MAXB 1184
#define K13 0.33333334f   /* fp32(1/3) */
#define K23 0.6666667f    /* fp32(2/3) */

__device__ unsigned g_pmin[MAXB];
__device__ unsigned g_pmax[MAXB];
__device__ unsigned g_count = 0;     // restored to 0 each run (graph-safe)
__device__ float2   g_norm;          // {scale, nbias = -xmin*scale}

__device__ __forceinline__ unsigned fenc(float f) {
    unsigned u = __float_as_uint(f);
    return (u & 0x80000000u) ? ~u : (u | 0x80000000u);
}
__device__ __forceinline__ float fdec(unsigned u) {
    return (u & 0x80000000u) ? __uint_as_float(u ^ 0x80000000u)
                             : __uint_as_float(~u);
}

__global__ void __launch_bounds__(256)
reduce_setup_kernel(const float* __restrict__ x, int n)
{
    float lmin =  3.4e38f, lmax = -3.4e38f;

    // ---- x scan: no dependency on any prior kernel; runs under PDL overlap
    int n4 = n >> 2;
    const float4* __restrict__ x4 = (const float4*)x;
    int stride = gridDim.x * blockDim.x;
    #pragma unroll 4
    for (int i = blockIdx.x * blockDim.x + threadIdx.x; i < n4; i += stride) {
        float4 v = x4[i];
        lmin = fminf(lmin, fminf(fminf(v.x, v.y), fminf(v.z, v.w)));
        lmax = fmaxf(lmax, fmaxf(fmaxf(v.x, v.y), fmaxf(v.z, v.w)));
    }
    for (int i = n4 * 4 + blockIdx.x * blockDim.x + threadIdx.x; i < n; i += stride) {
        float e = x[i];
        lmin = fminf(lmin, e); lmax = fmaxf(lmax, e);
    }

    unsigned emin = __reduce_min_sync(0xFFFFFFFFu, fenc(lmin));
    unsigned emax = __reduce_max_sync(0xFFFFFFFFu, fenc(lmax));

    __shared__ unsigned smin[8], smax[8];
    __shared__ bool is_last;
    int w = threadIdx.x >> 5;
    if ((threadIdx.x & 31) == 0) { smin[w] = emin; smax[w] = emax; }
    __syncthreads();

    // Before publishing shared state (g_pmin/g_count/g_norm), wait for the
    // preceding kernel (previous replay's main) to fully complete.
    cudaGridDependencySynchronize();

    if (threadIdx.x == 0) {
        int nw = blockDim.x >> 5;
        for (int i = 1; i < nw; i++) {
            emin = min(emin, smin[i]); emax = max(emax, smax[i]);
        }
        g_pmin[blockIdx.x] = emin;
        g_pmax[blockIdx.x] = emax;
        __threadfence();
        unsigned prev = atomicAdd(&g_count, 1u);
        is_last = (prev == gridDim.x - 1);
    }
    __syncthreads();
    if (!is_last) return;

    unsigned fmn = 0xFFFFFFFFu, fmx = 0u;
    int nb = gridDim.x;
    for (int i = threadIdx.x; i < nb; i += blockDim.x) {
        fmn = min(fmn, __ldcg(&g_pmin[i]));
        fmx = max(fmx, __ldcg(&g_pmax[i]));
    }
    fmn = __reduce_min_sync(0xFFFFFFFFu, fmn);
    fmx = __reduce_max_sync(0xFFFFFFFFu, fmx);
    if ((threadIdx.x & 31) == 0) { smin[w] = fmn; smax[w] = fmx; }
    __syncthreads();
    if (threadIdx.x == 0) {
        int nw = blockDim.x >> 5;
        for (int i = 1; i < nw; i++) {
            fmn = min(fmn, smin[i]); fmx = max(fmx, smax[i]);
        }
        float xmin = fdec(fmn);
        float xmax = fdec(fmx);
        float scale = 1.0f / (xmax - xmin + 1e-8f);
        g_norm = make_float2(scale, -xmin * scale);
        __threadfence();
        g_count = 0;
    }
}

// Closed-form cubic bases per span; coefficients are exact fp32 dyadics.
__device__ __forceinline__ void evalPoint(float u, float* __restrict__ o)
{
    if (u < K13) {
        float N0 = fmaf(u, -27.0f, 27.0f);  N0 = fmaf(u, N0, -9.0f);  N0 = fmaf(u, N0, 1.0f);
        float N1 = fmaf(u, 47.25f, -40.5f); N1 = fmaf(u, N1, 9.0f);   N1 = N1 * u;
        float N2 = fmaf(u, -24.75f, 13.5f); N2 = N2 * (u * u);
        float N3 = 4.5f * u * (u * u);
        o[0] = N0; o[1] = N1; o[2] = N2; o[3] = N3; o[4] = 0.0f; o[5] = 0.0f;
    } else if (u < K23) {
        float N1 = fmaf(u, -6.75f, 13.5f);   N1 = fmaf(u, N1, -9.0f);  N1 = fmaf(u, N1, 2.0f);
        float N2 = fmaf(u, 15.75f, -27.0f);  N2 = fmaf(u, N2, 13.5f);  N2 = fmaf(u, N2, -1.5f);
        float N3 = fmaf(u, -15.75f, 20.25f); N3 = fmaf(u, N3, -6.75f); N3 = fmaf(u, N3, 0.75f);
        float N4 = fmaf(u, 6.75f, -6.75f);   N4 = fmaf(u, N4, 2.25f);  N4 = fmaf(u, N4, -0.25f);
        o[0] = 0.0f; o[1] = N1; o[2] = N2; o[3] = N3; o[4] = N4; o[5] = 0.0f;
    } else {
        float w = 1.0f - u;
        float N5 = fmaf(w, -27.0f, 27.0f);  N5 = fmaf(w, N5, -9.0f);  N5 = fmaf(w, N5, 1.0f);
        float N4 = fmaf(w, 47.25f, -40.5f); N4 = fmaf(w, N4, 9.0f);   N4 = N4 * w;
        float N3 = fmaf(w, -24.75f, 13.5f); N3 = N3 * (w * w);
        float N2 = 4.5f * w * (w * w);
        o[0] = 0.0f; o[1] = 0.0f; o[2] = N2; o[3] = N3; o[4] = N4; o[5] = N5;
    }
}

// Per-warp staging: 32 lanes x 6 float4, padded to stride 7 per lane.
// Write (L = 6*lane + q -> slot 7*lane + q): conflict-free.
// Read  (L = q*32 + lane -> slot L + L/6): near-linear, rare 2-way.
#define WSTAGE 224

__global__ void __launch_bounds__(256)
bspline_main_kernel(const float* __restrict__ x,
                    float* __restrict__ out, int n)
{
    __shared__ float4 stage[8][WSTAGE];

    int lane = threadIdx.x & 31;
    int warp = threadIdx.x >> 5;
    int gwarp = blockIdx.x * 8 + warp;
    int wbase = gwarp * 128;             // first point of this warp

    if (wbase >= n) {
        cudaGridDependencySynchronize();
        return;
    }

    if (wbase + 128 <= n) {
        // Issue the x load BEFORE the dependency sync: it does not depend on
        // the reduction result, so it overlaps the reduce kernel's tail.
        float4 v = __ldg(((const float4*)x) + (wbase >> 2) + lane);

        cudaGridDependencySynchronize();      // g_norm now valid
        float2 nrm = g_norm;
        float scale = nrm.x, nb = nrm.y;

        float xs[4] = {v.x, v.y, v.z, v.w};
        float res[24];
        #pragma unroll
        for (int p = 0; p < 4; p++) {
            float u = fmaf(xs[p], scale, nb);
            evalPoint(u, &res[p * 6]);
        }

        float4* ws = stage[warp];
        #pragma unroll
        for (int q = 0; q < 6; q++)
            ws[7 * lane + q] = make_float4(res[4 * q], res[4 * q + 1],
                                           res[4 * q + 2], res[4 * q + 3]);
        __syncwarp();

        // coalesced streaming stores: 6 x STG.128, 16-B lane stride
        float4* o4 = (float4*)out + (size_t)wbase * 6 / 4;
        #pragma unroll
        for (int q = 0; q < 6; q++) {
            int L = q * 32 + lane;
            __stcs(o4 + L, ws[L + L / 6]);
        }
    } else {
        cudaGridDependencySynchronize();
        float2 nrm = g_norm;
        float scale = nrm.x, nb = nrm.y;
        // tail warp: scalar per-point
        for (int p = lane; p < 128; p += 32) {
            int idx = wbase + p;
            if (idx >= n) break;
            float u = fmaf(x[idx], scale, nb);
            float b6[6];
            evalPoint(u, b6);
            float* o = out + (size_t)idx * 6;
            #pragma unroll
            for (int j = 0; j < 6; j++) o[j] = b6[j];
        }
    }
}

extern "C" void kernel_launch(void* const* d_in, const int* in_sizes, int n_in,
                              void* d_out, int out_size)
{
    const float* x = (const float*)d_in[0];
    float* out     = (float*)d_out;
    int n = in_sizes[0];
    if (n <= 0) return;

    int n4 = n >> 2;
    int rblocks = (n4 + 255) / 256;
    if (rblocks > MAXB) rblocks = MAXB;
    if (rblocks < 1) rblocks = 1;

    // PDL on BOTH kernels:
    //  - reduce overlaps the previous graph replay's main-kernel drain
    //  - main overlaps the reduce kernel's tail
    cudaLaunchAttribute attr[1];
    attr[0].id = cudaLaunchAttributeProgrammaticStreamSerialization;
    attr[0].val.programmaticStreamSerializationAllowed = 1;

    cudaLaunchConfig_t rcfg = {};
    rcfg.gridDim  = dim3((unsigned)rblocks);
    rcfg.blockDim = dim3(256);
    rcfg.dynamicSmemBytes = 0;
    rcfg.stream = 0;
    rcfg.attrs = attr;
    rcfg.numAttrs = 1;
    if (cudaLaunchKernelEx(&rcfg, reduce_setup_kernel, x, n) != cudaSuccess)
        reduce_setup_kernel<<<rblocks, 256>>>(x, n);

    int npts_per_block = 1024;           // 8 warps * 128 pts
    int mblocks = (n + npts_per_block - 1) / npts_per_block;

    cudaLaunchConfig_t cfg = {};
    cfg.gridDim  = dim3((unsigned)mblocks);
    cfg.blockDim = dim3(256);
    cfg.dynamicSmemBytes = 0;
    cfg.stream = 0;
    cfg.attrs = attr;
    cfg.numAttrs = 1;
    if (cudaLaunchKernelEx(&cfg, bspline_main_kernel, x, out, n) != cudaSuccess)
        bspline_main_kernel<<<mblocks, 256>>>(x, out, n);
}

// round 16
// speedup vs baseline: 1.1472x; 1.0066x over previous
#include <cuda_runtime.h>
#include <cuda_bf16.h>

// ---------------------------------------------------------------------------
// BSplineBasis: out[N,6] = cubic B-spline basis of min-max-normalized x.
// Knots compile-time ([0,0,0,0,1/3,2/3,1,1,1,1]) => closed-form span cubics.
// Kernel 1: min/max reduction -> g_norm = {scale, -xmin*scale}.
// Kernel 2 (PDL, R11 structure): 8 pts/lane in TWO 4-pt transpose rounds
//   (both x loads issued up front, before cudaGridDependencySynchronize),
//   per-warp smem transpose (stride-7 pad), 6 lane-contiguous STG.128 per
//   round with .cs streaming (keeps x L2-resident across replays — the
//   measured reason .cs beats default/TMA stores on total time).
// ---------------------------------------------------------------------------

#define MAXB 1184
#define K13 0.33333334f   /* fp32(1/3) */
#define K23 0.6666667f    /* fp32(2/3) */

__device__ unsigned g_pmin[MAXB];
__device__ unsigned g_pmax[MAXB];
__device__ unsigned g_count = 0;     // restored to 0 each run (graph-safe)
__device__ float2   g_norm;          // {scale, nbias = -xmin*scale}

__device__ __forceinline__ unsigned fenc(float f) {
    unsigned u = __float_as_uint(f);
    return (u & 0x80000000u) ? ~u : (u | 0x80000000u);
}
__device__ __forceinline__ float fdec(unsigned u) {
    return (u & 0x80000000u) ? __uint_as_float(u ^ 0x80000000u)
                             : __uint_as_float(~u);
}

__global__ void __launch_bounds__(256)
reduce_setup_kernel(const float* __restrict__ x, int n)
{
    float lmin =  3.4e38f, lmax = -3.4e38f;

    int n4 = n >> 2;
    const float4* __restrict__ x4 = (const float4*)x;
    int stride = gridDim.x * blockDim.x;
    #pragma unroll 4
    for (int i = blockIdx.x * blockDim.x + threadIdx.x; i < n4; i += stride) {
        float4 v = x4[i];
        lmin = fminf(lmin, fminf(fminf(v.x, v.y), fminf(v.z, v.w)));
        lmax = fmaxf(lmax, fmaxf(fmaxf(v.x, v.y), fmaxf(v.z, v.w)));
    }
    for (int i = n4 * 4 + blockIdx.x * blockDim.x + threadIdx.x; i < n; i += stride) {
        float e = x[i];
        lmin = fminf(lmin, e); lmax = fmaxf(lmax, e);
    }

    unsigned emin = __reduce_min_sync(0xFFFFFFFFu, fenc(lmin));
    unsigned emax = __reduce_max_sync(0xFFFFFFFFu, fenc(lmax));

    __shared__ unsigned smin[8], smax[8];
    __shared__ bool is_last;
    int w = threadIdx.x >> 5;
    if ((threadIdx.x & 31) == 0) { smin[w] = emin; smax[w] = emax; }
    __syncthreads();
    if (threadIdx.x == 0) {
        int nw = blockDim.x >> 5;
        for (int i = 1; i < nw; i++) {
            emin = min(emin, smin[i]); emax = max(emax, smax[i]);
        }
        g_pmin[blockIdx.x] = emin;
        g_pmax[blockIdx.x] = emax;
        __threadfence();
        unsigned prev = atomicAdd(&g_count, 1u);
        is_last = (prev == gridDim.x - 1);
    }
    __syncthreads();
    if (!is_last) return;

    unsigned fmn = 0xFFFFFFFFu, fmx = 0u;
    int nb = gridDim.x;
    for (int i = threadIdx.x; i < nb; i += blockDim.x) {
        fmn = min(fmn, __ldcg(&g_pmin[i]));
        fmx = max(fmx, __ldcg(&g_pmax[i]));
    }
    fmn = __reduce_min_sync(0xFFFFFFFFu, fmn);
    fmx = __reduce_max_sync(0xFFFFFFFFu, fmx);
    if ((threadIdx.x & 31) == 0) { smin[w] = fmn; smax[w] = fmx; }
    __syncthreads();
    if (threadIdx.x == 0) {
        int nw = blockDim.x >> 5;
        for (int i = 1; i < nw; i++) {
            fmn = min(fmn, smin[i]); fmx = max(fmx, smax[i]);
        }
        float xmin = fdec(fmn);
        float xmax = fdec(fmx);
        float scale = 1.0f / (xmax - xmin + 1e-8f);
        g_norm = make_float2(scale, -xmin * scale);
        __threadfence();
        g_count = 0;
    }
}

// Closed-form cubic bases per span; coefficients are exact fp32 dyadics.
__device__ __forceinline__ void evalPoint(float u, float* __restrict__ o)
{
    if (u < K13) {
        float N0 = fmaf(u, -27.0f, 27.0f);  N0 = fmaf(u, N0, -9.0f);  N0 = fmaf(u, N0, 1.0f);
        float N1 = fmaf(u, 47.25f, -40.5f); N1 = fmaf(u, N1, 9.0f);   N1 = N1 * u;
        float N2 = fmaf(u, -24.75f, 13.5f); N2 = N2 * (u * u);
        float N3 = 4.5f * u * (u * u);
        o[0] = N0; o[1] = N1; o[2] = N2; o[3] = N3; o[4] = 0.0f; o[5] = 0.0f;
    } else if (u < K23) {
        float N1 = fmaf(u, -6.75f, 13.5f);   N1 = fmaf(u, N1, -9.0f);  N1 = fmaf(u, N1, 2.0f);
        float N2 = fmaf(u, 15.75f, -27.0f);  N2 = fmaf(u, N2, 13.5f);  N2 = fmaf(u, N2, -1.5f);
        float N3 = fmaf(u, -15.75f, 20.25f); N3 = fmaf(u, N3, -6.75f); N3 = fmaf(u, N3, 0.75f);
        float N4 = fmaf(u, 6.75f, -6.75f);   N4 = fmaf(u, N4, 2.25f);  N4 = fmaf(u, N4, -0.25f);
        o[0] = 0.0f; o[1] = N1; o[2] = N2; o[3] = N3; o[4] = N4; o[5] = 0.0f;
    } else {
        float w = 1.0f - u;
        float N5 = fmaf(w, -27.0f, 27.0f);  N5 = fmaf(w, N5, -9.0f);  N5 = fmaf(w, N5, 1.0f);
        float N4 = fmaf(w, 47.25f, -40.5f); N4 = fmaf(w, N4, 9.0f);   N4 = N4 * w;
        float N3 = fmaf(w, -24.75f, 13.5f); N3 = N3 * (w * w);
        float N2 = 4.5f * w * (w * w);
        o[0] = 0.0f; o[1] = 0.0f; o[2] = N2; o[3] = N3; o[4] = N4; o[5] = N5;
    }
}

// Per-warp staging: 32 lanes x 6 float4, padded to stride 7 per lane.
// Write (L = 6*lane + q -> slot 7*lane + q): conflict-free.
// Read  (L = q*32 + lane -> slot L + L/6): near-linear, rare 2-way.
#define WSTAGE 224

__global__ void __launch_bounds__(256)
bspline_main_kernel(const float* __restrict__ x,
                    float* __restrict__ out, int n)
{
    __shared__ float4 stage[8][WSTAGE];

    int lane = threadIdx.x & 31;
    int warp = threadIdx.x >> 5;
    int gwarp = blockIdx.x * 8 + warp;
    int wbase = gwarp * 256;             // 8 pts/lane: 256 pts per warp

    if (wbase >= n) {
        cudaGridDependencySynchronize();
        return;
    }

    if (wbase + 256 <= n) {
        // Issue BOTH x loads BEFORE the dependency sync (MLP=2): they do not
        // depend on the reduction result -> overlap the reduce kernel's tail.
        const float4* __restrict__ x4 = (const float4*)x;
        float4 va = __ldg(x4 + (wbase >> 2) + lane);          // pts [wbase, +128)
        float4 vb = __ldg(x4 + (wbase >> 2) + 32 + lane);     // pts [+128, +256)

        cudaGridDependencySynchronize();      // g_norm now valid
        float2 nrm = g_norm;
        float scale = nrm.x, nb = nrm.y;

        float4* ws = stage[warp];

        #pragma unroll
        for (int h = 0; h < 2; h++) {
            float4 v = h ? vb : va;
            float xs[4] = {v.x, v.y, v.z, v.w};
            float res[24];
            #pragma unroll
            for (int p = 0; p < 4; p++) {
                float u = fmaf(xs[p], scale, nb);
                evalPoint(u, &res[p * 6]);
            }

            if (h) __syncwarp();   // round-0 reads complete before overwrite
            #pragma unroll
            for (int q = 0; q < 6; q++)
                ws[7 * lane + q] = make_float4(res[4 * q], res[4 * q + 1],
                                               res[4 * q + 2], res[4 * q + 3]);
            __syncwarp();

            // coalesced streaming stores: 6 x STG.128, 16-B lane stride
            float4* o4 = (float4*)out + (size_t)(wbase + h * 128) * 6 / 4;
            #pragma unroll
            for (int q = 0; q < 6; q++) {
                int L = q * 32 + lane;
                __stcs(o4 + L, ws[L + L / 6]);
            }
        }
    } else {
        cudaGridDependencySynchronize();
        float2 nrm = g_norm;
        float scale = nrm.x, nb = nrm.y;
        // tail warp: scalar per-point
        for (int p = lane; p < 256; p += 32) {
            int idx = wbase + p;
            if (idx >= n) break;
            float u = fmaf(x[idx], scale, nb);
            float b6[6];
            evalPoint(u, b6);
            float* o = out + (size_t)idx * 6;
            #pragma unroll
            for (int j = 0; j < 6; j++) o[j] = b6[j];
        }
    }
}

extern "C" void kernel_launch(void* const* d_in, const int* in_sizes, int n_in,
                              void* d_out, int out_size)
{
    const float* x = (const float*)d_in[0];
    float* out     = (float*)d_out;
    int n = in_sizes[0];
    if (n <= 0) return;

    int n4 = n >> 2;
    int rblocks = (n4 + 255) / 256;
    if (rblocks > MAXB) rblocks = MAXB;
    if (rblocks < 1) rblocks = 1;
    reduce_setup_kernel<<<rblocks, 256>>>(x, n);

    int npts_per_block = 2048;           // 8 warps * 256 pts
    int mblocks = (n + npts_per_block - 1) / npts_per_block;

    // PDL launch: main kernel may begin before reduce fully completes;
    // cudaGridDependencySynchronize() inside provides the ordering.
    cudaLaunchConfig_t cfg = {};
    cfg.gridDim  = dim3((unsigned)mblocks);
    cfg.blockDim = dim3(256);
    cfg.dynamicSmemBytes = 0;
    cfg.stream = 0;
    cudaLaunchAttribute attr[1];
    attr[0].id = cudaLaunchAttributeProgrammaticStreamSerialization;
    attr[0].val.programmaticStreamSerializationAllowed = 1;
    cfg.attrs = attr;
    cfg.numAttrs = 1;
    cudaError_t err = cudaLaunchKernelEx(&cfg, bspline_main_kernel, x, out, n);
    if (err != cudaSuccess) {
        // fallback: plain serialized launch
        bspline_main_kernel<<<mblocks, 256>>>(x, out, n);
    }
}